// round 15
// baseline (speedup 1.0000x reference)
#include <cuda_runtime.h>
#include <cuda_fp16.h>
#include <cstdint>

// L1AttnSparse — GB300 sm_103a, round 15: R9 main kernel (best measured) +
// PDL (programmatic dependent launch) to overlap the fp16 convert pass with
// the main kernel's prologue and scheduling ramp.
// bs=2, n_tok=2048, n_heads=8, width=64, deg=32

#define BS   2
#define NTOK 2048
#define NH   8
#define WID  64
#define DEG  32
#define ROW  (NH * WID)            // 512 floats per token row
#define TOT  (BS * NTOK * ROW)     // 2,097,152 elements per tensor
#define U4TOK 128                  // uint4 per interleaved token row (2048B)
#define SCALE (-0.125f)            // -1/sqrt(64)

typedef unsigned long long u64;

// interleaved: token n -> [n*2048, +1024) = k row fp16, [+1024, +2048) = v row
__device__ __half2 g_kv[TOT];      // 8MB

__device__ __forceinline__ u64 pack2(float lo, float hi) {
    u64 r;
    asm("mov.b64 %0, {%1, %2};" : "=l"(r) : "f"(lo), "f"(hi));
    return r;
}
__device__ __forceinline__ float2 unpack2(u64 p) {
    float2 f;
    asm("mov.b64 {%0, %1}, %2;" : "=f"(f.x), "=f"(f.y) : "l"(p));
    return f;
}
__device__ __forceinline__ u64 add2(u64 a, u64 b) {
    u64 r;
    asm("add.rn.f32x2 %0, %1, %2;" : "=l"(r) : "l"(a), "l"(b));
    return r;
}

// convert: one thread -> one uint4 (8 halves) of k AND of v
__global__ __launch_bounds__(256)
void convert_kernel(const float* __restrict__ k, const float* __restrict__ v)
{
    // allow the dependent main kernel to begin launching immediately;
    // it gates its g_kv reads on cudaGridDependencySynchronize().
    cudaTriggerProgrammaticLaunchCompletion();

    const int j = blockIdx.x * blockDim.x + threadIdx.x;   // uint4 slot id
    const int n = j >> 6;              // token (64 k-uint4 per token)
    const int s = j & 63;              // slot within row
    const float4* kp = (const float4*)(k + (size_t)n * ROW + s * 8);
    const float4* vp = (const float4*)(v + (size_t)n * ROW + s * 8);
    const float4 k0 = kp[0], k1 = kp[1];
    const float4 v0 = vp[0], v1 = vp[1];
    union { __half2 h[4]; uint4 u; } ok, ov;
    ok.h[0] = __floats2half2_rn(k0.x, k0.y);
    ok.h[1] = __floats2half2_rn(k0.z, k0.w);
    ok.h[2] = __floats2half2_rn(k1.x, k1.y);
    ok.h[3] = __floats2half2_rn(k1.z, k1.w);
    ov.h[0] = __floats2half2_rn(v0.x, v0.y);
    ov.h[1] = __floats2half2_rn(v0.z, v0.w);
    ov.h[2] = __floats2half2_rn(v1.x, v1.y);
    ov.h[3] = __floats2half2_rn(v1.z, v1.w);
    uint4* base = (uint4*)g_kv + (size_t)n * U4TOK;
    base[s]      = ok.u;
    base[s + 64] = ov.u;
}

__global__ __launch_bounds__(256)
void l1attn_sparse_kernel(const float* __restrict__ q,
                          const int*   __restrict__ coo,
                          float*       __restrict__ out)
{
    const int t    = blockIdx.x;       // token
    const int b    = blockIdx.y;       // batch
    const int tid  = threadIdx.x;      // 0..255
    const int h    = tid >> 5;         // warp = head
    const int lane = tid & 31;
    const int qt   = lane >> 3;        // edge quarter (0..3)
    const int c    = lane & 7;         // 8-col (16B) chunk within head row

    // ---- KV-independent prologue: runs while convert_kernel still executes ----
    const int dst   = __ldg(&coo[3 * (t * DEG)]);
    const int myoff = __ldg(&coo[3 * (t * DEG + lane) + 1]) * U4TOK;

    const size_t qbase = ((size_t)(b * NTOK + dst)) * ROW;
    const float4 qa = *(const float4*)(q + qbase + h * WID + 8 * c);
    const float4 qb = *(const float4*)(q + qbase + h * WID + 8 * c + 4);
    const __half2 qh0 = __floats2half2_rn(qa.x, qa.y);
    const __half2 qh1 = __floats2half2_rn(qa.z, qa.w);
    const __half2 qh2 = __floats2half2_rn(qb.x, qb.y);
    const __half2 qh3 = __floats2half2_rn(qb.z, qb.w);

    const uint4* kvbase = (const uint4*)g_kv + (size_t)(b * NTOK) * U4TOK + h * 8 + c;

    // edge offsets for this lane's quarter (edges 4i+qt), via shuffle
    int koff[8];
#pragma unroll
    for (int i = 0; i < 8; ++i)
        koff[i] = __shfl_sync(0xFFFFFFFFu, myoff, 4 * i + qt);

    // ---- wait for convert_kernel's writes to g_kv to be complete/visible ----
    cudaGridDependencySynchronize();

    // ---- Phase 2: 8 iterations, 4 edges per warp-load ----
    float d[8];
#pragma unroll
    for (int i = 0; i < 8; ++i) {
        const uint4 kr = kvbase[koff[i]];
        const __half2 d0 = __habs2(__hsub2(qh0, *(const __half2*)&kr.x));
        const __half2 d1 = __habs2(__hsub2(qh1, *(const __half2*)&kr.y));
        const __half2 d2 = __habs2(__hsub2(qh2, *(const __half2*)&kr.z));
        const __half2 d3 = __habs2(__hsub2(qh3, *(const __half2*)&kr.w));
        const __half2 s01 = __hadd2(d0, d1);           // one fp16 add level
        const __half2 s23 = __hadd2(d2, d3);
        const float2 f0 = __half22float2(s01);
        const float2 f1 = __half22float2(s23);
        const float2 fs = unpack2(add2(pack2(f0.x, f0.y), pack2(f1.x, f1.y)));
        d[i] = fs.x + fs.y;
    }

    // ---- multi-reduce d[8] within each 8-lane group (7 shuffles) ----
    // lane ends holding the full score of edge  e(lane) = 4*(lane&7) + (lane>>3)
#pragma unroll
    for (int o = 4; o >= 1; o >>= 1) {
        const bool hi = (lane & o) != 0;
#pragma unroll
        for (int i = 0; i < o; ++i) {
            const float keep = hi ? d[i + o] : d[i];
            const float send = hi ? d[i]     : d[i + o];
            d[i] = keep + __shfl_xor_sync(0xFFFFFFFFu, send, o);
        }
    }

    // ---- Phase 3: softmax, no max subtraction (scores bounded, fp32 safe) ----
    const float e = __expf(d[0] * SCALE);
    float s = e;
#pragma unroll
    for (int o = 16; o > 0; o >>= 1)
        s += __shfl_xor_sync(0xFFFFFFFFu, s, o);
    const float wgt = e * __fdividef(1.0f, s);

    // weights for edges 4i+qt as half2 (lane i | (lane & 24))
    __half2 wh[8];
#pragma unroll
    for (int i = 0; i < 8; ++i)
        wh[i] = __float2half2_rn(__shfl_sync(0xFFFFFFFFu, wgt, i | (lane & 24)));

    // ---- Phase 4: HFMA2 accumulation, even/odd edge split for precision ----
    const __half2 hz = __float2half2_rn(0.f);
    __half2 aE0 = hz, aE1 = hz, aE2 = hz, aE3 = hz;
    __half2 aO0 = hz, aO1 = hz, aO2 = hz, aO3 = hz;
#pragma unroll
    for (int i = 0; i < 8; i += 2) {
        const uint4 ve = kvbase[koff[i] + 64];
        aE0 = __hfma2(*(const __half2*)&ve.x, wh[i], aE0);
        aE1 = __hfma2(*(const __half2*)&ve.y, wh[i], aE1);
        aE2 = __hfma2(*(const __half2*)&ve.z, wh[i], aE2);
        aE3 = __hfma2(*(const __half2*)&ve.w, wh[i], aE3);
        const uint4 vo = kvbase[koff[i + 1] + 64];
        aO0 = __hfma2(*(const __half2*)&vo.x, wh[i + 1], aO0);
        aO1 = __hfma2(*(const __half2*)&vo.y, wh[i + 1], aO1);
        aO2 = __hfma2(*(const __half2*)&vo.z, wh[i + 1], aO2);
        aO3 = __hfma2(*(const __half2*)&vo.w, wh[i + 1], aO3);
    }

    // combine even/odd partials in fp32 (packed)
    u64 acc0, acc1, acc2, acc3;
    {
        const float2 e0 = __half22float2(aE0), o0 = __half22float2(aO0);
        const float2 e1 = __half22float2(aE1), o1 = __half22float2(aO1);
        const float2 e2 = __half22float2(aE2), o2 = __half22float2(aO2);
        const float2 e3 = __half22float2(aE3), o3 = __half22float2(aO3);
        acc0 = add2(pack2(e0.x, e0.y), pack2(o0.x, o0.y));
        acc1 = add2(pack2(e1.x, e1.y), pack2(o1.x, o1.y));
        acc2 = add2(pack2(e2.x, e2.y), pack2(o2.x, o2.y));
        acc3 = add2(pack2(e3.x, e3.y), pack2(o3.x, o3.y));
    }

    // ---- epilogue multi-reduce across quarters (bits 3,4), packed ----
    const bool b3 = (lane & 8)  != 0;
    const bool b4 = (lane & 16) != 0;
    {
        const u64 keepA = b3 ? acc2 : acc0;
        const u64 sendA = b3 ? acc0 : acc2;
        const u64 keepB = b3 ? acc3 : acc1;
        const u64 sendB = b3 ? acc1 : acc3;
        const float2 sa = unpack2(sendA);
        const float2 sb = unpack2(sendB);
        const u64 shA = pack2(__shfl_xor_sync(0xFFFFFFFFu, sa.x, 8),
                              __shfl_xor_sync(0xFFFFFFFFu, sa.y, 8));
        const u64 shB = pack2(__shfl_xor_sync(0xFFFFFFFFu, sb.x, 8),
                              __shfl_xor_sync(0xFFFFFFFFu, sb.y, 8));
        acc0 = add2(keepA, shA);
        acc1 = add2(keepB, shB);
    }
    {
        const u64 keep = b4 ? acc1 : acc0;
        const u64 send = b4 ? acc0 : acc1;
        const float2 sv = unpack2(send);
        const u64 sh = pack2(__shfl_xor_sync(0xFFFFFFFFu, sv.x, 16),
                             __shfl_xor_sync(0xFFFFFFFFu, sv.y, 16));
        acc0 = add2(keep, sh);
    }

    // lane owns output cols 8c + 4*b3 + 2*b4 + {0,1}
    const int ocol = 8 * c + (b3 ? 4 : 0) + (b4 ? 2 : 0);
    const float2 res = unpack2(acc0);
    *(float2*)(out + qbase + h * WID + ocol) = res;
}

extern "C" void kernel_launch(void* const* d_in, const int* in_sizes, int n_in,
                              void* d_out, int out_size)
{
    const float* q   = (const float*)d_in[0];
    const float* k   = (const float*)d_in[1];
    const float* v   = (const float*)d_in[2];
    const int*   coo = (const int*)d_in[3];
    float*       out = (float*)d_out;

    // primary: convert (triggers launch completion at entry)
    convert_kernel<<<TOT / 8 / 256, 256>>>(k, v);

    // secondary: main kernel with programmatic stream serialization —
    // may begin launching while convert is still running; it gates its
    // g_kv reads on cudaGridDependencySynchronize().
    cudaLaunchConfig_t cfg = {};
    cfg.gridDim  = dim3(NTOK, BS);
    cfg.blockDim = dim3(256);
    cudaLaunchAttribute attr[1];
    attr[0].id = cudaLaunchAttributeProgrammaticStreamSerialization;
    attr[0].val.programmaticStreamSerializationAllowed = 1;
    cfg.attrs    = attr;
    cfg.numAttrs = 1;
    cudaLaunchKernelEx(&cfg, l1attn_sparse_kernel, q, coo, out);
}

// round 16
// speedup vs baseline: 1.0013x; 1.0013x over previous
#include <cuda_runtime.h>
#include <cuda_fp16.h>
#include <cstdint>

// L1AttnSparse — GB300 sm_103a, round 16: R9 main kernel (best measured) with
// __launch_bounds__(256,6) reg cap -> 6 blocks/SM for latency hiding.
// bs=2, n_tok=2048, n_heads=8, width=64, deg=32
// Warp = head; 8 lanes per edge; interleaved fp16 KV staging buffer
// (k at [0], v at +1024B). HFMA2 phase-4 accumulation with even/odd split.

#define BS   2
#define NTOK 2048
#define NH   8
#define WID  64
#define DEG  32
#define ROW  (NH * WID)            // 512 floats per token row
#define TOT  (BS * NTOK * ROW)     // 2,097,152 elements per tensor
#define U4TOK 128                  // uint4 per interleaved token row (2048B)
#define SCALE (-0.125f)            // -1/sqrt(64)

typedef unsigned long long u64;

// interleaved: token n -> [n*2048, +1024) = k row fp16, [+1024, +2048) = v row
__device__ __half2 g_kv[TOT];      // 8MB

__device__ __forceinline__ u64 pack2(float lo, float hi) {
    u64 r;
    asm("mov.b64 %0, {%1, %2};" : "=l"(r) : "f"(lo), "f"(hi));
    return r;
}
__device__ __forceinline__ float2 unpack2(u64 p) {
    float2 f;
    asm("mov.b64 {%0, %1}, %2;" : "=f"(f.x), "=f"(f.y) : "l"(p));
    return f;
}
__device__ __forceinline__ u64 add2(u64 a, u64 b) {
    u64 r;
    asm("add.rn.f32x2 %0, %1, %2;" : "=l"(r) : "l"(a), "l"(b));
    return r;
}

// convert: one thread -> one uint4 (8 halves) of k AND of v
__global__ __launch_bounds__(256)
void convert_kernel(const float* __restrict__ k, const float* __restrict__ v)
{
    const int j = blockIdx.x * blockDim.x + threadIdx.x;   // uint4 slot id
    const int n = j >> 6;              // token (64 k-uint4 per token)
    const int s = j & 63;              // slot within row
    const float4* kp = (const float4*)(k + (size_t)n * ROW + s * 8);
    const float4* vp = (const float4*)(v + (size_t)n * ROW + s * 8);
    const float4 k0 = kp[0], k1 = kp[1];
    const float4 v0 = vp[0], v1 = vp[1];
    union { __half2 h[4]; uint4 u; } ok, ov;
    ok.h[0] = __floats2half2_rn(k0.x, k0.y);
    ok.h[1] = __floats2half2_rn(k0.z, k0.w);
    ok.h[2] = __floats2half2_rn(k1.x, k1.y);
    ok.h[3] = __floats2half2_rn(k1.z, k1.w);
    ov.h[0] = __floats2half2_rn(v0.x, v0.y);
    ov.h[1] = __floats2half2_rn(v0.z, v0.w);
    ov.h[2] = __floats2half2_rn(v1.x, v1.y);
    ov.h[3] = __floats2half2_rn(v1.z, v1.w);
    uint4* base = (uint4*)g_kv + (size_t)n * U4TOK;
    base[s]      = ok.u;
    base[s + 64] = ov.u;
}

__global__ __launch_bounds__(256, 6)
void l1attn_sparse_kernel(const float* __restrict__ q,
                          const int*   __restrict__ coo,
                          float*       __restrict__ out)
{
    const int t    = blockIdx.x;       // token
    const int b    = blockIdx.y;       // batch
    const int tid  = threadIdx.x;      // 0..255
    const int h    = tid >> 5;         // warp = head
    const int lane = tid & 31;
    const int qt   = lane >> 3;        // edge quarter (0..3)
    const int c    = lane & 7;         // 8-col (16B) chunk within head row

    // per-lane coo src (L1 hits across warps), kept in register
    const int dst   = __ldg(&coo[3 * (t * DEG)]);
    const int myoff = __ldg(&coo[3 * (t * DEG + lane) + 1]) * U4TOK;

    // q chunk (8 cols) -> 4 half2 registers
    const size_t qbase = ((size_t)(b * NTOK + dst)) * ROW;
    const float4 qa = *(const float4*)(q + qbase + h * WID + 8 * c);
    const float4 qb = *(const float4*)(q + qbase + h * WID + 8 * c + 4);
    const __half2 qh0 = __floats2half2_rn(qa.x, qa.y);
    const __half2 qh1 = __floats2half2_rn(qa.z, qa.w);
    const __half2 qh2 = __floats2half2_rn(qb.x, qb.y);
    const __half2 qh3 = __floats2half2_rn(qb.z, qb.w);

    const uint4* kvbase = (const uint4*)g_kv + (size_t)(b * NTOK) * U4TOK + h * 8 + c;

    // edge offsets for this lane's quarter (edges 4i+qt), via shuffle
    int koff[8];
#pragma unroll
    for (int i = 0; i < 8; ++i)
        koff[i] = __shfl_sync(0xFFFFFFFFu, myoff, 4 * i + qt);

    // ---- Phase 2: 8 iterations, 4 edges per warp-load ----
    float d[8];
#pragma unroll
    for (int i = 0; i < 8; ++i) {
        const uint4 kr = kvbase[koff[i]];
        const __half2 d0 = __habs2(__hsub2(qh0, *(const __half2*)&kr.x));
        const __half2 d1 = __habs2(__hsub2(qh1, *(const __half2*)&kr.y));
        const __half2 d2 = __habs2(__hsub2(qh2, *(const __half2*)&kr.z));
        const __half2 d3 = __habs2(__hsub2(qh3, *(const __half2*)&kr.w));
        const __half2 s01 = __hadd2(d0, d1);           // one fp16 add level
        const __half2 s23 = __hadd2(d2, d3);
        const float2 f0 = __half22float2(s01);
        const float2 f1 = __half22float2(s23);
        const float2 fs = unpack2(add2(pack2(f0.x, f0.y), pack2(f1.x, f1.y)));
        d[i] = fs.x + fs.y;
    }

    // ---- multi-reduce d[8] within each 8-lane group (7 shuffles) ----
    // lane ends holding the full score of edge  e(lane) = 4*(lane&7) + (lane>>3)
#pragma unroll
    for (int o = 4; o >= 1; o >>= 1) {
        const bool hi = (lane & o) != 0;
#pragma unroll
        for (int i = 0; i < o; ++i) {
            const float keep = hi ? d[i + o] : d[i];
            const float send = hi ? d[i]     : d[i + o];
            d[i] = keep + __shfl_xor_sync(0xFFFFFFFFu, send, o);
        }
    }

    // ---- Phase 3: softmax, no max subtraction (scores bounded, fp32 safe) ----
    const float e = __expf(d[0] * SCALE);
    float s = e;
#pragma unroll
    for (int o = 16; o > 0; o >>= 1)
        s += __shfl_xor_sync(0xFFFFFFFFu, s, o);
    const float wgt = e * __fdividef(1.0f, s);

    // weights for edges 4i+qt as half2 (lane i | (lane & 24))
    __half2 wh[8];
#pragma unroll
    for (int i = 0; i < 8; ++i)
        wh[i] = __float2half2_rn(__shfl_sync(0xFFFFFFFFu, wgt, i | (lane & 24)));

    // ---- Phase 4: HFMA2 accumulation, even/odd edge split for precision ----
    const __half2 hz = __float2half2_rn(0.f);
    __half2 aE0 = hz, aE1 = hz, aE2 = hz, aE3 = hz;
    __half2 aO0 = hz, aO1 = hz, aO2 = hz, aO3 = hz;
#pragma unroll
    for (int i = 0; i < 8; i += 2) {
        const uint4 ve = kvbase[koff[i] + 64];
        aE0 = __hfma2(*(const __half2*)&ve.x, wh[i], aE0);
        aE1 = __hfma2(*(const __half2*)&ve.y, wh[i], aE1);
        aE2 = __hfma2(*(const __half2*)&ve.z, wh[i], aE2);
        aE3 = __hfma2(*(const __half2*)&ve.w, wh[i], aE3);
        const uint4 vo = kvbase[koff[i + 1] + 64];
        aO0 = __hfma2(*(const __half2*)&vo.x, wh[i + 1], aO0);
        aO1 = __hfma2(*(const __half2*)&vo.y, wh[i + 1], aO1);
        aO2 = __hfma2(*(const __half2*)&vo.z, wh[i + 1], aO2);
        aO3 = __hfma2(*(const __half2*)&vo.w, wh[i + 1], aO3);
    }

    // combine even/odd partials in fp32 (packed)
    u64 acc0, acc1, acc2, acc3;
    {
        const float2 e0 = __half22float2(aE0), o0 = __half22float2(aO0);
        const float2 e1 = __half22float2(aE1), o1 = __half22float2(aO1);
        const float2 e2 = __half22float2(aE2), o2 = __half22float2(aO2);
        const float2 e3 = __half22float2(aE3), o3 = __half22float2(aO3);
        acc0 = add2(pack2(e0.x, e0.y), pack2(o0.x, o0.y));
        acc1 = add2(pack2(e1.x, e1.y), pack2(o1.x, o1.y));
        acc2 = add2(pack2(e2.x, e2.y), pack2(o2.x, o2.y));
        acc3 = add2(pack2(e3.x, e3.y), pack2(o3.x, o3.y));
    }

    // ---- epilogue multi-reduce across quarters (bits 3,4), packed ----
    const bool b3 = (lane & 8)  != 0;
    const bool b4 = (lane & 16) != 0;
    {
        const u64 keepA = b3 ? acc2 : acc0;
        const u64 sendA = b3 ? acc0 : acc2;
        const u64 keepB = b3 ? acc3 : acc1;
        const u64 sendB = b3 ? acc1 : acc3;
        const float2 sa = unpack2(sendA);
        const float2 sb = unpack2(sendB);
        const u64 shA = pack2(__shfl_xor_sync(0xFFFFFFFFu, sa.x, 8),
                              __shfl_xor_sync(0xFFFFFFFFu, sa.y, 8));
        const u64 shB = pack2(__shfl_xor_sync(0xFFFFFFFFu, sb.x, 8),
                              __shfl_xor_sync(0xFFFFFFFFu, sb.y, 8));
        acc0 = add2(keepA, shA);
        acc1 = add2(keepB, shB);
    }
    {
        const u64 keep = b4 ? acc1 : acc0;
        const u64 send = b4 ? acc0 : acc1;
        const float2 sv = unpack2(send);
        const u64 sh = pack2(__shfl_xor_sync(0xFFFFFFFFu, sv.x, 16),
                             __shfl_xor_sync(0xFFFFFFFFu, sv.y, 16));
        acc0 = add2(keep, sh);
    }

    // lane owns output cols 8c + 4*b3 + 2*b4 + {0,1}
    const int ocol = 8 * c + (b3 ? 4 : 0) + (b4 ? 2 : 0);
    const float2 res = unpack2(acc0);
    *(float2*)(out + qbase + h * WID + ocol) = res;
}

extern "C" void kernel_launch(void* const* d_in, const int* in_sizes, int n_in,
                              void* d_out, int out_size)
{
    const float* q   = (const float*)d_in[0];
    const float* k   = (const float*)d_in[1];
    const float* v   = (const float*)d_in[2];
    const int*   coo = (const int*)d_in[3];
    float*       out = (float*)d_out;

    convert_kernel<<<TOT / 8 / 256, 256>>>(k, v);
    dim3 grid(NTOK, BS);
    l1attn_sparse_kernel<<<grid, 256>>>(q, coo, out);
}

// round 17
// speedup vs baseline: 1.1000x; 1.0986x over previous
#include <cuda_runtime.h>
#include <cuda_fp16.h>
#include <cstdint>

// L1AttnSparse — GB300 sm_103a, round 17: R9 (best main) + packed-shuffle
// reductions: score multi-reduce 7->4 shfl, weight distribution 8->5 shfl.
// bs=2, n_tok=2048, n_heads=8, width=64, deg=32

#define BS   2
#define NTOK 2048
#define NH   8
#define WID  64
#define DEG  32
#define ROW  (NH * WID)            // 512 floats per token row
#define TOT  (BS * NTOK * ROW)     // 2,097,152 elements per tensor
#define U4TOK 128                  // uint4 per interleaved token row (2048B)
#define SCALE (-0.125f)            // -1/sqrt(64)

typedef unsigned long long u64;
typedef unsigned int       u32;

// interleaved: token n -> [n*2048, +1024) = k row fp16, [+1024, +2048) = v row
__device__ __half2 g_kv[TOT];      // 8MB

__device__ __forceinline__ u64 pack2(float lo, float hi) {
    u64 r;
    asm("mov.b64 %0, {%1, %2};" : "=l"(r) : "f"(lo), "f"(hi));
    return r;
}
__device__ __forceinline__ float2 unpack2(u64 p) {
    float2 f;
    asm("mov.b64 {%0, %1}, %2;" : "=f"(f.x), "=f"(f.y) : "l"(p));
    return f;
}
__device__ __forceinline__ u64 add2(u64 a, u64 b) {
    u64 r;
    asm("add.rn.f32x2 %0, %1, %2;" : "=l"(r) : "l"(a), "l"(b));
    return r;
}
// packed 2xf32 xor-shuffle: 2 values per SHFL via register-pair aliasing
__device__ __forceinline__ u64 shfl_xor2(u64 v, int m) {
    const float2 f = unpack2(v);
    return pack2(__shfl_xor_sync(0xFFFFFFFFu, f.x, m),
                 __shfl_xor_sync(0xFFFFFFFFu, f.y, m));
}

// convert: one thread -> one uint4 (8 halves) of k AND of v
__global__ __launch_bounds__(256)
void convert_kernel(const float* __restrict__ k, const float* __restrict__ v)
{
    const int j = blockIdx.x * blockDim.x + threadIdx.x;   // uint4 slot id
    const int n = j >> 6;              // token (64 k-uint4 per token)
    const int s = j & 63;              // slot within row
    const float4* kp = (const float4*)(k + (size_t)n * ROW + s * 8);
    const float4* vp = (const float4*)(v + (size_t)n * ROW + s * 8);
    const float4 k0 = kp[0], k1 = kp[1];
    const float4 v0 = vp[0], v1 = vp[1];
    union { __half2 h[4]; uint4 u; } ok, ov;
    ok.h[0] = __floats2half2_rn(k0.x, k0.y);
    ok.h[1] = __floats2half2_rn(k0.z, k0.w);
    ok.h[2] = __floats2half2_rn(k1.x, k1.y);
    ok.h[3] = __floats2half2_rn(k1.z, k1.w);
    ov.h[0] = __floats2half2_rn(v0.x, v0.y);
    ov.h[1] = __floats2half2_rn(v0.z, v0.w);
    ov.h[2] = __floats2half2_rn(v1.x, v1.y);
    ov.h[3] = __floats2half2_rn(v1.z, v1.w);
    uint4* base = (uint4*)g_kv + (size_t)n * U4TOK;
    base[s]      = ok.u;
    base[s + 64] = ov.u;
}

__global__ __launch_bounds__(256)
void l1attn_sparse_kernel(const float* __restrict__ q,
                          const int*   __restrict__ coo,
                          float*       __restrict__ out)
{
    const int t    = blockIdx.x;       // token
    const int b    = blockIdx.y;       // batch
    const int tid  = threadIdx.x;      // 0..255
    const int h    = tid >> 5;         // warp = head
    const int lane = tid & 31;
    const int qt   = lane >> 3;        // edge quarter (0..3)
    const int c    = lane & 7;         // 8-col (16B) chunk within head row

    // per-lane coo src (L1 hits across warps), kept in register
    const int dst   = __ldg(&coo[3 * (t * DEG)]);
    const int myoff = __ldg(&coo[3 * (t * DEG + lane) + 1]) * U4TOK;

    // q chunk (8 cols) -> 4 half2 registers
    const size_t qbase = ((size_t)(b * NTOK + dst)) * ROW;
    const float4 qa = *(const float4*)(q + qbase + h * WID + 8 * c);
    const float4 qb = *(const float4*)(q + qbase + h * WID + 8 * c + 4);
    const __half2 qh0 = __floats2half2_rn(qa.x, qa.y);
    const __half2 qh1 = __floats2half2_rn(qa.z, qa.w);
    const __half2 qh2 = __floats2half2_rn(qb.x, qb.y);
    const __half2 qh3 = __floats2half2_rn(qb.z, qb.w);

    const uint4* kvbase = (const uint4*)g_kv + (size_t)(b * NTOK) * U4TOK + h * 8 + c;

    // edge offsets for this lane's quarter (edges 4i+qt), via shuffle
    int koff[8];
#pragma unroll
    for (int i = 0; i < 8; ++i)
        koff[i] = __shfl_sync(0xFFFFFFFFu, myoff, 4 * i + qt);

    // ---- Phase 2: 8 iterations, 4 edges per warp-load ----
    float d[8];
#pragma unroll
    for (int i = 0; i < 8; ++i) {
        const uint4 kr = kvbase[koff[i]];
        const __half2 d0 = __habs2(__hsub2(qh0, *(const __half2*)&kr.x));
        const __half2 d1 = __habs2(__hsub2(qh1, *(const __half2*)&kr.y));
        const __half2 d2 = __habs2(__hsub2(qh2, *(const __half2*)&kr.z));
        const __half2 d3 = __habs2(__hsub2(qh3, *(const __half2*)&kr.w));
        const __half2 s01 = __hadd2(d0, d1);           // one fp16 add level
        const __half2 s23 = __hadd2(d2, d3);
        const float2 f0 = __half22float2(s01);
        const float2 f1 = __half22float2(s23);
        const float2 fs = unpack2(add2(pack2(f0.x, f0.y), pack2(f1.x, f1.y)));
        d[i] = fs.x + fs.y;
    }

    // ---- packed multi-reduce d[8] within 8-lane groups: 4 shfl total ----
    // level o=4: send 4 values as 2 packed shuffles
    {
        const bool hi = (lane & 4) != 0;
        const float k0 = hi ? d[4] : d[0], s0 = hi ? d[0] : d[4];
        const float k1 = hi ? d[5] : d[1], s1 = hi ? d[1] : d[5];
        const float k2 = hi ? d[6] : d[2], s2 = hi ? d[2] : d[6];
        const float k3 = hi ? d[7] : d[3], s3 = hi ? d[3] : d[7];
        const float2 r0 = unpack2(shfl_xor2(pack2(s0, s1), 4) );
        const float2 r1 = unpack2(shfl_xor2(pack2(s2, s3), 4) );
        d[0] = k0 + r0.x;  d[1] = k1 + r0.y;
        d[2] = k2 + r1.x;  d[3] = k3 + r1.y;
    }
    // level o=2: send 2 values as 1 packed shuffle
    {
        const bool hi = (lane & 2) != 0;
        const float k0 = hi ? d[2] : d[0], s0 = hi ? d[0] : d[2];
        const float k1 = hi ? d[3] : d[1], s1 = hi ? d[1] : d[3];
        const float2 r = unpack2(shfl_xor2(pack2(s0, s1), 2));
        d[0] = k0 + r.x;  d[1] = k1 + r.y;
    }
    // level o=1: 1 scalar shuffle
    {
        const bool hi = (lane & 1) != 0;
        const float keep = hi ? d[1] : d[0];
        const float send = hi ? d[0] : d[1];
        d[0] = keep + __shfl_xor_sync(0xFFFFFFFFu, send, 1);
    }
    // lane holds full score of edge  e(lane) = 4*(lane&7) + (lane>>3)

    // ---- Phase 3: softmax, no max subtraction (scores bounded, fp32 safe) ----
    const float e = __expf(d[0] * SCALE);
    float s = e;
#pragma unroll
    for (int o = 16; o > 0; o >>= 1)
        s += __shfl_xor_sync(0xFFFFFFFFu, s, o);
    const float wgt = e * __fdividef(1.0f, s);

    // ---- packed weight distribution: 5 shfl instead of 8 ----
    // pair lane with lane^1: h2 = (w_edge(4i+qt), w_edge(4(i+1)+qt)), i even
    const float wother = __shfl_xor_sync(0xFFFFFFFFu, wgt, 1);
    const __half2 wpair_mine = (lane & 1)
        ? __floats2half2_rn(wother, wgt)
        : __floats2half2_rn(wgt, wother);
    // fetch 4 pairs covering edges 4*(0..7)+qt from lanes 2j | (lane&24)
    __half2 wh[8];
#pragma unroll
    for (int jj = 0; jj < 4; ++jj) {
        const u32 p = __shfl_sync(0xFFFFFFFFu,
                                  *(const u32*)&wpair_mine,
                                  (2 * jj) | (lane & 24));
        const __half2 hp = *(const __half2*)&p;
        wh[2 * jj]     = __half2half2(__low2half(hp));
        wh[2 * jj + 1] = __half2half2(__high2half(hp));
    }

    // ---- Phase 4: HFMA2 accumulation, even/odd edge split for precision ----
    const __half2 hz = __float2half2_rn(0.f);
    __half2 aE0 = hz, aE1 = hz, aE2 = hz, aE3 = hz;
    __half2 aO0 = hz, aO1 = hz, aO2 = hz, aO3 = hz;
#pragma unroll
    for (int i = 0; i < 8; i += 2) {
        const uint4 ve = kvbase[koff[i] + 64];
        aE0 = __hfma2(*(const __half2*)&ve.x, wh[i], aE0);
        aE1 = __hfma2(*(const __half2*)&ve.y, wh[i], aE1);
        aE2 = __hfma2(*(const __half2*)&ve.z, wh[i], aE2);
        aE3 = __hfma2(*(const __half2*)&ve.w, wh[i], aE3);
        const uint4 vo = kvbase[koff[i + 1] + 64];
        aO0 = __hfma2(*(const __half2*)&vo.x, wh[i + 1], aO0);
        aO1 = __hfma2(*(const __half2*)&vo.y, wh[i + 1], aO1);
        aO2 = __hfma2(*(const __half2*)&vo.z, wh[i + 1], aO2);
        aO3 = __hfma2(*(const __half2*)&vo.w, wh[i + 1], aO3);
    }

    // combine even/odd partials in fp32 (packed)
    u64 acc0, acc1, acc2, acc3;
    {
        const float2 e0 = __half22float2(aE0), o0 = __half22float2(aO0);
        const float2 e1 = __half22float2(aE1), o1 = __half22float2(aO1);
        const float2 e2 = __half22float2(aE2), o2 = __half22float2(aO2);
        const float2 e3 = __half22float2(aE3), o3 = __half22float2(aO3);
        acc0 = add2(pack2(e0.x, e0.y), pack2(o0.x, o0.y));
        acc1 = add2(pack2(e1.x, e1.y), pack2(o1.x, o1.y));
        acc2 = add2(pack2(e2.x, e2.y), pack2(o2.x, o2.y));
        acc3 = add2(pack2(e3.x, e3.y), pack2(o3.x, o3.y));
    }

    // ---- epilogue multi-reduce across quarters (bits 3,4), packed ----
    const bool b3 = (lane & 8)  != 0;
    const bool b4 = (lane & 16) != 0;
    {
        const u64 keepA = b3 ? acc2 : acc0;
        const u64 sendA = b3 ? acc0 : acc2;
        const u64 keepB = b3 ? acc3 : acc1;
        const u64 sendB = b3 ? acc1 : acc3;
        acc0 = add2(keepA, shfl_xor2(sendA, 8));
        acc1 = add2(keepB, shfl_xor2(sendB, 8));
    }
    {
        const u64 keep = b4 ? acc1 : acc0;
        const u64 send = b4 ? acc0 : acc1;
        acc0 = add2(keep, shfl_xor2(send, 16));
    }

    // lane owns output cols 8c + 4*b3 + 2*b4 + {0,1}
    const int ocol = 8 * c + (b3 ? 4 : 0) + (b4 ? 2 : 0);
    const float2 res = unpack2(acc0);
    *(float2*)(out + qbase + h * WID + ocol) = res;
}

extern "C" void kernel_launch(void* const* d_in, const int* in_sizes, int n_in,
                              void* d_out, int out_size)
{
    const float* q   = (const float*)d_in[0];
    const float* k   = (const float*)d_in[1];
    const float* v   = (const float*)d_in[2];
    const int*   coo = (const int*)d_in[3];
    float*       out = (float*)d_out;

    convert_kernel<<<TOT / 8 / 256, 256>>>(k, v);
    dim3 grid(NTOK, BS);
    l1attn_sparse_kernel<<<grid, 256>>>(q, coo, out);
}